// round 1
// baseline (speedup 1.0000x reference)
#include <cuda_runtime.h>
#include <math.h>

// Problem constants (fixed by the reference: B=4, N=2048, DIM=512, H=1)
#define CB 4
#define CN 2048
#define CD 512
#define C5 (5 * CD)   // 2560
#define C2 (2 * CD)   // 1024

// ---------------------------------------------------------------------------
// Scratch: __device__ globals (allocation inside kernel_launch is forbidden).
// Total ~490 MB, fine on 192 GB HBM3e.
// ---------------------------------------------------------------------------
static __device__ float g_P [(size_t)CB * CN * C5];   // qkvvv projection [B,N,2560]
static __device__ float g_X [(size_t)CB * CN * CN];   // X, later M1 (in place)
static __device__ float g_Y [(size_t)CB * CN * CN];
static __device__ float g_Z [(size_t)CB * CN * CN];
static __device__ float g_XY[(size_t)CB * CN * CN];   // XY, later M2 (in place)
static __device__ float g_YZ[(size_t)CB * CN * CN];
static __device__ float g_n1[(size_t)CB * CN * CD];
static __device__ float g_n2[(size_t)CB * CN * CD];
static __device__ float g_dn[(size_t)CB * CN];
static __device__ float g_u [(size_t)CB * CN * C2];

// ---------------------------------------------------------------------------
// Generic fp32 tiled GEMM.
//   NT=true : C[i,j] = f( sum_k A[i,k] * B[j,k] )   (A row-major, B row-major)
//   NT=false: C[i,j] = f( sum_k A[i,k] * B[k,j] )
// f: optional exp(escale * s) and/or + bias[j].
// Batched via blockIdx.z with element strides sA/sB/sC.
// REQUIRES: M,N multiples of 128; K multiple of 8; lda/ldb multiples of 4;
// base pointers 16B-aligned. All call sites below satisfy this.
// ---------------------------------------------------------------------------
template <bool NT, bool DO_EXP, bool DO_BIAS>
__global__ __launch_bounds__(256, 2)
void gemm_k(const float* __restrict__ A, const float* __restrict__ B,
            float* __restrict__ C,
            int M, int N, int K, int lda, int ldb, int ldc,
            size_t sA, size_t sB, size_t sC,
            float escale, const float* __restrict__ bias)
{
    constexpr int BM = 128, BN = 128, BK = 8, TM = 8, TN = 8;
    __shared__ float As[BK][BM + 4];
    __shared__ float Bs[BK][BN + 4];

    A += (size_t)blockIdx.z * sA;
    B += (size_t)blockIdx.z * sB;
    C += (size_t)blockIdx.z * sC;

    const int tid = threadIdx.x;
    const int tx  = tid & 15;    // N direction (16 threads)
    const int ty  = tid >> 4;    // M direction (16 threads)
    const int m0  = blockIdx.y * BM;
    const int n0  = blockIdx.x * BN;

    // A-tile (and NT B-tile) loader mapping: 128 rows x 8 cols, one float4/thread
    const int arow = tid >> 1;          // 0..127
    const int acol = (tid & 1) * 4;     // 0 or 4
    // NN B-tile loader mapping: 8 rows x 128 cols
    const int brow = tid >> 5;          // 0..7
    const int bcol = (tid & 31) * 4;    // 0..124

    float acc[TM][TN];
#pragma unroll
    for (int i = 0; i < TM; i++)
#pragma unroll
        for (int j = 0; j < TN; j++) acc[i][j] = 0.f;

    for (int k0 = 0; k0 < K; k0 += BK) {
        float4 av = *reinterpret_cast<const float4*>(
            &A[(size_t)(m0 + arow) * lda + k0 + acol]);
        As[acol + 0][arow] = av.x;
        As[acol + 1][arow] = av.y;
        As[acol + 2][arow] = av.z;
        As[acol + 3][arow] = av.w;
        if (NT) {
            float4 bv = *reinterpret_cast<const float4*>(
                &B[(size_t)(n0 + arow) * ldb + k0 + acol]);
            Bs[acol + 0][arow] = bv.x;
            Bs[acol + 1][arow] = bv.y;
            Bs[acol + 2][arow] = bv.z;
            Bs[acol + 3][arow] = bv.w;
        } else {
            float4 bv = *reinterpret_cast<const float4*>(
                &B[(size_t)(k0 + brow) * ldb + n0 + bcol]);
            Bs[brow][bcol + 0] = bv.x;
            Bs[brow][bcol + 1] = bv.y;
            Bs[brow][bcol + 2] = bv.z;
            Bs[brow][bcol + 3] = bv.w;
        }
        __syncthreads();

#pragma unroll
        for (int k = 0; k < BK; k++) {
            float rA[TM], rB[TN];
#pragma unroll
            for (int m = 0; m < TM; m++) rA[m] = As[k][ty * TM + m];
#pragma unroll
            for (int n = 0; n < TN; n++) rB[n] = Bs[k][tx * TN + n];
#pragma unroll
            for (int m = 0; m < TM; m++)
#pragma unroll
                for (int n = 0; n < TN; n++)
                    acc[m][n] = fmaf(rA[m], rB[n], acc[m][n]);
        }
        __syncthreads();
    }

#pragma unroll
    for (int m = 0; m < TM; m++) {
        const int row = m0 + ty * TM + m;
#pragma unroll
        for (int n = 0; n < TN; n++) {
            const int col = n0 + tx * TN + n;
            float v = acc[m][n];
            if (DO_EXP)  v = __expf(escale * v);
            if (DO_BIAS) v += bias[col];
            C[(size_t)row * ldc + col] = v;
        }
    }
}

// ---------------------------------------------------------------------------
// In-place transposed Hadamard: Aio[b][i][j] *= T[b][j][i]
// ---------------------------------------------------------------------------
__global__ void mulT_k(float* __restrict__ Aio, const float* __restrict__ T, int n)
{
    __shared__ float sm[32][33];
    const int b  = blockIdx.z;
    const int i0 = blockIdx.y * 32;
    const int j0 = blockIdx.x * 32;
    const int tx = threadIdx.x;   // 0..31
    const int ty = threadIdx.y;   // 0..7
    const float* Tb = T   + (size_t)b * n * n;
    float*       Ab = Aio + (size_t)b * n * n;

#pragma unroll
    for (int r = ty; r < 32; r += 8)
        sm[r][tx] = Tb[(size_t)(j0 + r) * n + i0 + tx];   // sm[jr][ic] = T[j0+jr][i0+ic]
    __syncthreads();
#pragma unroll
    for (int r = ty; r < 32; r += 8)
        Ab[(size_t)(i0 + r) * n + j0 + tx] *= sm[tx][r];  // needs T[j0+tx][i0+r]
}

// ---------------------------------------------------------------------------
// Row sums: den[row] = sum_j A[row][j], one block per row, 256 threads.
// ---------------------------------------------------------------------------
__global__ void rowsum_k(const float* __restrict__ A, float* __restrict__ den, int n)
{
    const int row = blockIdx.x;
    const float* a = A + (size_t)row * n;
    float s = 0.f;
    for (int j = threadIdx.x; j < n; j += blockDim.x) s += a[j];
#pragma unroll
    for (int o = 16; o; o >>= 1) s += __shfl_down_sync(0xffffffffu, s, o);
    __shared__ float sm[8];
    if ((threadIdx.x & 31) == 0) sm[threadIdx.x >> 5] = s;
    __syncthreads();
    if (threadIdx.x < 8) {
        s = sm[threadIdx.x];
#pragma unroll
        for (int o = 4; o; o >>= 1) s += __shfl_down_sync(0xffu, s, o);
        if (threadIdx.x == 0) den[row] = s;
    }
}

// ---------------------------------------------------------------------------
// u[row, 0:512] = n1[row]/den[row]; u[row, 512:1024] = n2[row]/den[row]
// ---------------------------------------------------------------------------
__global__ void build_u_k(const float* __restrict__ n1, const float* __restrict__ n2,
                          const float* __restrict__ den, float* __restrict__ u)
{
    const size_t total = (size_t)CB * CN * C2;
    for (size_t i = (size_t)blockIdx.x * blockDim.x + threadIdx.x; i < total;
         i += (size_t)gridDim.x * blockDim.x) {
        const size_t row = i >> 10;          // / 1024
        const int    c   = (int)(i & 1023);
        const float  d   = den[row];
        const float  v   = (c < CD) ? n1[row * CD + c] : n2[row * CD + (c - CD)];
        u[i] = v / d;
    }
}

// ---------------------------------------------------------------------------
extern "C" void kernel_launch(void* const* d_in, const int* in_sizes, int n_in,
                              void* d_out, int out_size)
{
    const float* x  = (const float*)d_in[0];   // [4,2048,512]
    const float* w  = (const float*)d_in[1];   // [2560,512]
    const float* ow = (const float*)d_in[2];   // [512,1024]
    const float* ob = (const float*)d_in[3];   // [512]
    float* out = (float*)d_out;                // [4,2048,512]

    float *P, *X, *Y, *Z, *XY, *YZ, *n1, *n2, *dn, *u;
    cudaGetSymbolAddress((void**)&P,  g_P);
    cudaGetSymbolAddress((void**)&X,  g_X);
    cudaGetSymbolAddress((void**)&Y,  g_Y);
    cudaGetSymbolAddress((void**)&Z,  g_Z);
    cudaGetSymbolAddress((void**)&XY, g_XY);
    cudaGetSymbolAddress((void**)&YZ, g_YZ);
    cudaGetSymbolAddress((void**)&n1, g_n1);
    cudaGetSymbolAddress((void**)&n2, g_n2);
    cudaGetSymbolAddress((void**)&dn, g_dn);
    cudaGetSymbolAddress((void**)&u,  g_u);

    const float scale = 1.0f / sqrtf((float)CD);   // D^-0.5
    const size_t sP  = (size_t)CN * C5;            // per-batch stride in P
    const size_t sNN = (size_t)CN * CN;
    const size_t sND = (size_t)CN * CD;

    // 1. P = x @ w^T : [8192,2560] = [8192,512] x [2560,512]^T
    gemm_k<true, false, false><<<dim3(C5 / 128, (CB * CN) / 128, 1), 256>>>(
        x, w, P, CB * CN, C5, CD, CD, CD, C5, 0, 0, 0, 1.f, nullptr);

    // 2. X = exp(s * a b^T), Y = exp(s * b c^T), Z = exp(s * c a^T)  (batched)
    dim3 gScore(CN / 128, CN / 128, CB);
    gemm_k<true, true, false><<<gScore, 256>>>(P + 0 * CD, P + 1 * CD, X,
        CN, CN, CD, C5, C5, CN, sP, sP, sNN, scale, nullptr);
    gemm_k<true, true, false><<<gScore, 256>>>(P + 1 * CD, P + 2 * CD, Y,
        CN, CN, CD, C5, C5, CN, sP, sP, sNN, scale, nullptr);
    gemm_k<true, true, false><<<gScore, 256>>>(P + 2 * CD, P + 0 * CD, Z,
        CN, CN, CD, C5, C5, CN, sP, sP, sNN, scale, nullptr);

    // 3. XY = X @ Y ; YZ = Y @ Z   (batched NN, 2048^3)
    gemm_k<false, false, false><<<gScore, 256>>>(X, Y, XY,
        CN, CN, CN, CN, CN, CN, sNN, sNN, sNN, 1.f, nullptr);
    gemm_k<false, false, false><<<gScore, 256>>>(Y, Z, YZ,
        CN, CN, CN, CN, CN, CN, sNN, sNN, sNN, 1.f, nullptr);

    // 4. M1 = X .* YZ^T (in X);  M2 = XY .* Z^T (in XY)
    dim3 gT(CN / 32, CN / 32, CB), bT(32, 8);
    mulT_k<<<gT, bT>>>(X,  YZ, CN);
    mulT_k<<<gT, bT>>>(XY, Z,  CN);

    // 5. den = rowsum(M1)
    rowsum_k<<<CB * CN, 256>>>(X, dn, CN);

    // 6. n1 = M1 @ v1 ; n2 = M2 @ v2   (v1/v2 are strided views of P)
    dim3 gNV(CD / 128, CN / 128, CB);
    gemm_k<false, false, false><<<gNV, 256>>>(X, P + 3 * CD, n1,
        CN, CD, CN, CN, C5, CD, sNN, sP, sND, 1.f, nullptr);
    gemm_k<false, false, false><<<gNV, 256>>>(XY, P + 4 * CD, n2,
        CN, CD, CN, CN, C5, CD, sNN, sP, sND, 1.f, nullptr);

    // 7. u = [n1/den, n2/den]
    build_u_k<<<8192, 256>>>(n1, n2, dn, u);

    // 8. out = u @ ow^T + ob : [8192,512]
    gemm_k<true, false, true><<<dim3(CD / 128, (CB * CN) / 128, 1), 256>>>(
        u, ow, out, CB * CN, CD, C2, C2, C2, CD, 0, 0, 0, 1.f, ob);
}

// round 2
// speedup vs baseline: 3.2452x; 3.2452x over previous
#include <cuda_runtime.h>
#include <math.h>
#include <stdint.h>

// Problem constants (fixed: B=4, N=2048, DIM=512, H=1)
#define CB 4
#define CN 2048
#define CD 512
#define C5 (5 * CD)   // 2560
#define C2 (2 * CD)   // 1024

// ---------------------------------------------------------------------------
// Scratch (__device__ globals; allocation in kernel_launch is forbidden).
// ---------------------------------------------------------------------------
static __device__ float g_P [(size_t)CB * CN * C5];
static __device__ float g_X [(size_t)CB * CN * CN];   // X, later M1 in place
static __device__ float g_Y [(size_t)CB * CN * CN];
static __device__ float g_Z [(size_t)CB * CN * CN];
static __device__ float g_XY[(size_t)CB * CN * CN];   // XY, later M2 in place
static __device__ float g_YZ[(size_t)CB * CN * CN];
static __device__ float g_n1[(size_t)CB * CN * CD];
static __device__ float g_n2[(size_t)CB * CN * CD];
static __device__ float g_dn[(size_t)CB * CN];
static __device__ float g_u [(size_t)CB * CN * C2];

__device__ __forceinline__ uint32_t smem_u32(const void* p) {
    return (uint32_t)__cvta_generic_to_shared(p);
}

__device__ __forceinline__ void cp16(uint32_t s, const void* g) {
    asm volatile("cp.async.cg.shared.global [%0], [%1], 16;\n" :: "r"(s), "l"(g));
}
__device__ __forceinline__ void cp_commit() {
    asm volatile("cp.async.commit_group;\n");
}

__device__ __forceinline__ void mma_tf32(float* c, const uint32_t* a, const uint32_t* b) {
    asm volatile(
        "mma.sync.aligned.m16n8k8.row.col.f32.tf32.tf32.f32 "
        "{%0,%1,%2,%3}, {%4,%5,%6,%7}, {%8,%9}, {%0,%1,%2,%3};\n"
        : "+f"(c[0]), "+f"(c[1]), "+f"(c[2]), "+f"(c[3])
        : "r"(a[0]), "r"(a[1]), "r"(a[2]), "r"(a[3]), "r"(b[0]), "r"(b[1]));
}

// ---------------------------------------------------------------------------
// TF32 tensor-core GEMM, 128x128x16 tile, 8 warps (32x64 warp tiles),
// 2-stage cp.async pipeline.
//   NT=true : C[i,j] = f( sum_k A[i,k] * B[j,k] )
//   NT=false: C[i,j] = f( sum_k A[i,k] * B[k,j] )
// REQUIRES: M,N mult of 128; K mult of 16; lda/ldb mult of 4; 16B-aligned.
// ---------------------------------------------------------------------------
template <bool NT, bool DO_EXP, bool DO_BIAS>
__global__ __launch_bounds__(256, 2)
void gemm_tc(const float* __restrict__ A, const float* __restrict__ B,
             float* __restrict__ C, int K, int lda, int ldb, int ldc,
             size_t sA, size_t sB, size_t sC,
             float escale, const float* __restrict__ bias)
{
    constexpr int BM = 128, BN = 128, BK = 16;
    constexpr int SA  = 20;    // As row stride (m-major), conflict-free frag loads
    constexpr int SBT = 20;    // NT Bs row stride (n-major)
    constexpr int SBN = 136;   // NN Bs row stride (k-major)
    constexpr int BSZ = NT ? (BN * SBT) : (BK * SBN);

    __shared__ float As[2][BM * SA];
    __shared__ float Bs[2][BSZ];

    A += (size_t)blockIdx.z * sA;
    B += (size_t)blockIdx.z * sB;
    C += (size_t)blockIdx.z * sC;

    const int tid  = threadIdx.x;
    const int m0   = blockIdx.y * BM;
    const int n0   = blockIdx.x * BN;
    const int lane = tid & 31;
    const int warp = tid >> 5;
    const int wm   = warp & 3;         // 4 warps along M
    const int wn   = warp >> 2;        // 2 warps along N
    const int mb   = wm * 32;
    const int nb   = wn * 64;
    const int g8   = lane >> 2;        // 0..7
    const int t4   = lane & 3;         // 0..3

    float acc[2][8][4];
#pragma unroll
    for (int mt = 0; mt < 2; mt++)
#pragma unroll
        for (int nt = 0; nt < 8; nt++)
#pragma unroll
            for (int r = 0; r < 4; r++) acc[mt][nt][r] = 0.f;

    auto load_stage = [&](int st, int kk) {
#pragma unroll
        for (int t = 0; t < 2; t++) {                 // A: 128x16, 512 float4
            int idx = t * 256 + tid;
            int r = idx >> 2, c = (idx & 3) * 4;
            cp16(smem_u32(&As[st][r * SA + c]),
                 &A[(size_t)(m0 + r) * lda + kk + c]);
        }
        if (NT) {
#pragma unroll
            for (int t = 0; t < 2; t++) {             // B: 128x16 (n-major)
                int idx = t * 256 + tid;
                int r = idx >> 2, c = (idx & 3) * 4;
                cp16(smem_u32(&Bs[st][r * SBT + c]),
                     &B[(size_t)(n0 + r) * ldb + kk + c]);
            }
        } else {
#pragma unroll
            for (int t = 0; t < 2; t++) {             // B: 16x128 (k-major)
                int idx = t * 256 + tid;
                int r = idx >> 5, c = (idx & 31) * 4;
                cp16(smem_u32(&Bs[st][r * SBN + c]),
                     &B[(size_t)(kk + r) * ldb + n0 + c]);
            }
        }
        cp_commit();
    };

    auto compute_stage = [&](int st) {
#pragma unroll
        for (int ks = 0; ks < 2; ks++) {
            const int k0 = ks * 8;
            uint32_t a[2][4];
#pragma unroll
            for (int mt = 0; mt < 2; mt++) {
                const int m = mb + mt * 16;
                a[mt][0] = __float_as_uint(As[st][(m + g8)     * SA + k0 + t4]);
                a[mt][1] = __float_as_uint(As[st][(m + g8 + 8) * SA + k0 + t4]);
                a[mt][2] = __float_as_uint(As[st][(m + g8)     * SA + k0 + t4 + 4]);
                a[mt][3] = __float_as_uint(As[st][(m + g8 + 8) * SA + k0 + t4 + 4]);
            }
            uint32_t b[8][2];
#pragma unroll
            for (int nt = 0; nt < 8; nt++) {
                const int n = nb + nt * 8;
                if (NT) {
                    b[nt][0] = __float_as_uint(Bs[st][(n + g8) * SBT + k0 + t4]);
                    b[nt][1] = __float_as_uint(Bs[st][(n + g8) * SBT + k0 + t4 + 4]);
                } else {
                    b[nt][0] = __float_as_uint(Bs[st][(k0 + t4)     * SBN + n + g8]);
                    b[nt][1] = __float_as_uint(Bs[st][(k0 + t4 + 4) * SBN + n + g8]);
                }
            }
#pragma unroll
            for (int mt = 0; mt < 2; mt++)
#pragma unroll
                for (int nt = 0; nt < 8; nt++)
                    mma_tf32(acc[mt][nt], a[mt], b[nt]);
        }
    };

    const int nChunks = K / BK;
    load_stage(0, 0);
    for (int ch = 0; ch < nChunks; ch++) {
        if (ch + 1 < nChunks) {
            load_stage((ch + 1) & 1, (ch + 1) * BK);
            asm volatile("cp.async.wait_group 1;\n");
        } else {
            asm volatile("cp.async.wait_group 0;\n");
        }
        __syncthreads();
        compute_stage(ch & 1);
        __syncthreads();
    }

    // Epilogue
#pragma unroll
    for (int mt = 0; mt < 2; mt++) {
#pragma unroll
        for (int nt = 0; nt < 8; nt++) {
            const int row = m0 + mb + mt * 16 + g8;
            const int col = n0 + nb + nt * 8 + t4 * 2;
#pragma unroll
            for (int h = 0; h < 2; h++) {            // h=0: rows, h=1: rows+8
                float v0 = acc[mt][nt][2 * h + 0];
                float v1 = acc[mt][nt][2 * h + 1];
                if (DO_EXP)  { v0 = __expf(escale * v0); v1 = __expf(escale * v1); }
                if (DO_BIAS) { v0 += bias[col]; v1 += bias[col + 1]; }
                *reinterpret_cast<float2*>(&C[(size_t)(row + 8 * h) * ldc + col]) =
                    make_float2(v0, v1);
            }
        }
    }
}

// ---------------------------------------------------------------------------
// In-place transposed Hadamard: Aio[b][i][j] *= T[b][j][i]
// ---------------------------------------------------------------------------
__global__ void mulT_k(float* __restrict__ Aio, const float* __restrict__ T, int n)
{
    __shared__ float sm[32][33];
    const int b  = blockIdx.z;
    const int i0 = blockIdx.y * 32;
    const int j0 = blockIdx.x * 32;
    const int tx = threadIdx.x;
    const int ty = threadIdx.y;
    const float* Tb = T   + (size_t)b * n * n;
    float*       Ab = Aio + (size_t)b * n * n;

#pragma unroll
    for (int r = ty; r < 32; r += 8)
        sm[r][tx] = Tb[(size_t)(j0 + r) * n + i0 + tx];
    __syncthreads();
#pragma unroll
    for (int r = ty; r < 32; r += 8)
        Ab[(size_t)(i0 + r) * n + j0 + tx] *= sm[tx][r];
}

// ---------------------------------------------------------------------------
__global__ void rowsum_k(const float* __restrict__ A, float* __restrict__ den, int n)
{
    const int row = blockIdx.x;
    const float* a = A + (size_t)row * n;
    float s = 0.f;
    for (int j = threadIdx.x; j < n; j += blockDim.x) s += a[j];
#pragma unroll
    for (int o = 16; o; o >>= 1) s += __shfl_down_sync(0xffffffffu, s, o);
    __shared__ float sm[8];
    if ((threadIdx.x & 31) == 0) sm[threadIdx.x >> 5] = s;
    __syncthreads();
    if (threadIdx.x < 8) {
        s = sm[threadIdx.x];
#pragma unroll
        for (int o = 4; o; o >>= 1) s += __shfl_down_sync(0xffu, s, o);
        if (threadIdx.x == 0) den[row] = s;
    }
}

// ---------------------------------------------------------------------------
__global__ void build_u_k(const float* __restrict__ n1, const float* __restrict__ n2,
                          const float* __restrict__ den, float* __restrict__ u)
{
    const size_t total = (size_t)CB * CN * C2;
    for (size_t i = (size_t)blockIdx.x * blockDim.x + threadIdx.x; i < total;
         i += (size_t)gridDim.x * blockDim.x) {
        const size_t row = i >> 10;
        const int    c   = (int)(i & 1023);
        const float  d   = den[row];
        const float  v   = (c < CD) ? n1[row * CD + c] : n2[row * CD + (c - CD)];
        u[i] = v / d;
    }
}

// ---------------------------------------------------------------------------
extern "C" void kernel_launch(void* const* d_in, const int* in_sizes, int n_in,
                              void* d_out, int out_size)
{
    const float* x  = (const float*)d_in[0];   // [4,2048,512]
    const float* w  = (const float*)d_in[1];   // [2560,512]
    const float* ow = (const float*)d_in[2];   // [512,1024]
    const float* ob = (const float*)d_in[3];   // [512]
    float* out = (float*)d_out;                // [4,2048,512]

    float *P, *X, *Y, *Z, *XY, *YZ, *n1, *n2, *dn, *u;
    cudaGetSymbolAddress((void**)&P,  g_P);
    cudaGetSymbolAddress((void**)&X,  g_X);
    cudaGetSymbolAddress((void**)&Y,  g_Y);
    cudaGetSymbolAddress((void**)&Z,  g_Z);
    cudaGetSymbolAddress((void**)&XY, g_XY);
    cudaGetSymbolAddress((void**)&YZ, g_YZ);
    cudaGetSymbolAddress((void**)&n1, g_n1);
    cudaGetSymbolAddress((void**)&n2, g_n2);
    cudaGetSymbolAddress((void**)&dn, g_dn);
    cudaGetSymbolAddress((void**)&u,  g_u);

    const float scale = 1.0f / sqrtf((float)CD);
    const size_t sP  = (size_t)CN * C5;
    const size_t sNN = (size_t)CN * CN;
    const size_t sND = (size_t)CN * CD;

    // 1. P = x @ w^T : [8192,2560]
    gemm_tc<true, false, false><<<dim3(C5 / 128, (CB * CN) / 128, 1), 256>>>(
        x, w, P, CD, CD, CD, C5, 0, 0, 0, 1.f, nullptr);

    // 2. X/Y/Z = exp(scale * pairwise NT), batched over B
    dim3 gScore(CN / 128, CN / 128, CB);
    gemm_tc<true, true, false><<<gScore, 256>>>(P + 0 * CD, P + 1 * CD, X,
        CD, C5, C5, CN, sP, sP, sNN, scale, nullptr);
    gemm_tc<true, true, false><<<gScore, 256>>>(P + 1 * CD, P + 2 * CD, Y,
        CD, C5, C5, CN, sP, sP, sNN, scale, nullptr);
    gemm_tc<true, true, false><<<gScore, 256>>>(P + 2 * CD, P + 0 * CD, Z,
        CD, C5, C5, CN, sP, sP, sNN, scale, nullptr);

    // 3. XY = X @ Y ; YZ = Y @ Z  (batched NN, 2048^3)
    gemm_tc<false, false, false><<<gScore, 256>>>(X, Y, XY,
        CN, CN, CN, CN, sNN, sNN, sNN, 1.f, nullptr);
    gemm_tc<false, false, false><<<gScore, 256>>>(Y, Z, YZ,
        CN, CN, CN, CN, sNN, sNN, sNN, 1.f, nullptr);

    // 4. M1 = X .* YZ^T (in X);  M2 = XY .* Z^T (in XY)
    dim3 gT(CN / 32, CN / 32, CB), bT(32, 8);
    mulT_k<<<gT, bT>>>(X,  YZ, CN);
    mulT_k<<<gT, bT>>>(XY, Z,  CN);

    // 5. den = rowsum(M1)
    rowsum_k<<<CB * CN, 256>>>(X, dn, CN);

    // 6. n1 = M1 @ v1 ; n2 = M2 @ v2 (v1/v2 strided views of P)
    dim3 gNV(CD / 128, CN / 128, CB);
    gemm_tc<false, false, false><<<gNV, 256>>>(X, P + 3 * CD, n1,
        CN, CN, C5, CD, sNN, sP, sND, 1.f, nullptr);
    gemm_tc<false, false, false><<<gNV, 256>>>(XY, P + 4 * CD, n2,
        CN, CN, C5, CD, sNN, sP, sND, 1.f, nullptr);

    // 7. u = [n1/den, n2/den]
    build_u_k<<<8192, 256>>>(n1, n2, dn, u);

    // 8. out = u @ ow^T + ob
    gemm_tc<true, false, true><<<dim3(CD / 128, (CB * CN) / 128, 1), 256>>>(
        u, ow, out, C2, C2, C2, CD, 0, 0, 0, 1.f, ob);
}

// round 5
// speedup vs baseline: 4.7612x; 1.4671x over previous
#include <cuda_runtime.h>
#include <cuda_fp16.h>
#include <cuda_bf16.h>
#include <math.h>
#include <stdint.h>

// Problem constants (fixed: B=4, N=2048, DIM=512, H=1)
#define CB 4
#define CN 2048
#define CD 512
#define C5 (5 * CD)   // 2560
#define C2 (2 * CD)   // 1024

#define BM 128
#define BN 128
#define BK 32
#define TILE_B (128 * 80)            // one operand tile: 128 rows x 80 B
#define STAGE_H (2 * TILE_B)         // plain kernel stage (A + B)
#define NST_H 4
#define SMEM_H (NST_H * STAGE_H)     // 81920
#define STAGE_S (4 * TILE_B)         // split kernel stage (Ah,Al,Bh,Bl)
#define NST_S 3
#define SMEM_S (NST_S * STAGE_S)     // 122880

typedef __half       f16;
typedef __nv_bfloat16 bf16;

// ---------------------------------------------------------------------------
// Scratch (__device__ globals)
// ---------------------------------------------------------------------------
static __device__ bf16  g_xh [(size_t)CB * CN * CD];
static __device__ bf16  g_xl [(size_t)CB * CN * CD];
static __device__ bf16  g_wh [(size_t)C5 * CD];
static __device__ bf16  g_wl [(size_t)C5 * CD];
static __device__ bf16  g_owh[(size_t)CD * C2];
static __device__ bf16  g_owl[(size_t)CD * C2];
static __device__ f16   g_P16[(size_t)CB * CN * C5];
static __device__ float g_Pf [(size_t)CB * CN * C5];
static __device__ f16   g_X16[(size_t)CB * CN * CN];
static __device__ float g_Xf [(size_t)CB * CN * CN];
static __device__ f16   g_Y16[(size_t)CB * CN * CN];
static __device__ f16   g_Yt16[(size_t)CB * CN * CN];
static __device__ f16   g_Zt16[(size_t)CB * CN * CN];
static __device__ float g_Ztf[(size_t)CB * CN * CN];
static __device__ float g_XYf[(size_t)CB * CN * CN];
static __device__ float g_YZtf[(size_t)CB * CN * CN];
static __device__ bf16  g_M1h[(size_t)CB * CN * CN];
static __device__ bf16  g_M1l[(size_t)CB * CN * CN];
static __device__ bf16  g_M2h[(size_t)CB * CN * CN];
static __device__ bf16  g_M2l[(size_t)CB * CN * CN];
static __device__ bf16  g_v1th[(size_t)CB * CD * CN];
static __device__ bf16  g_v1tl[(size_t)CB * CD * CN];
static __device__ bf16  g_v2th[(size_t)CB * CD * CN];
static __device__ bf16  g_v2tl[(size_t)CB * CD * CN];
static __device__ float g_n1 [(size_t)CB * CN * CD];
static __device__ float g_n2 [(size_t)CB * CN * CD];
static __device__ float g_dn [(size_t)CB * CN];
static __device__ bf16  g_uh [(size_t)CB * CN * C2];
static __device__ bf16  g_ul [(size_t)CB * CN * C2];

// ---------------------------------------------------------------------------
// PTX helpers
// ---------------------------------------------------------------------------
__device__ __forceinline__ uint32_t smem_u32(const void* p) {
    return (uint32_t)__cvta_generic_to_shared(p);
}
__device__ __forceinline__ void cp16(uint32_t s, const void* g) {
    asm volatile("cp.async.cg.shared.global [%0], [%1], 16;\n" :: "r"(s), "l"(g));
}
__device__ __forceinline__ void ldsm4(uint32_t& r0, uint32_t& r1, uint32_t& r2,
                                      uint32_t& r3, uint32_t a) {
    asm volatile("ldmatrix.sync.aligned.m8n8.x4.shared.b16 {%0,%1,%2,%3}, [%4];"
        : "=r"(r0), "=r"(r1), "=r"(r2), "=r"(r3) : "r"(a));
}
__device__ __forceinline__ void mma_f16m(float* c, const uint32_t* a, const uint32_t* b) {
    asm volatile(
        "mma.sync.aligned.m16n8k16.row.col.f32.f16.f16.f32 "
        "{%0,%1,%2,%3}, {%4,%5,%6,%7}, {%8,%9}, {%0,%1,%2,%3};\n"
        : "+f"(c[0]), "+f"(c[1]), "+f"(c[2]), "+f"(c[3])
        : "r"(a[0]), "r"(a[1]), "r"(a[2]), "r"(a[3]), "r"(b[0]), "r"(b[1]));
}
__device__ __forceinline__ void mma_bfm(float* c, const uint32_t* a, const uint32_t* b) {
    asm volatile(
        "mma.sync.aligned.m16n8k16.row.col.f32.bf16.bf16.f32 "
        "{%0,%1,%2,%3}, {%4,%5,%6,%7}, {%8,%9}, {%0,%1,%2,%3};\n"
        : "+f"(c[0]), "+f"(c[1]), "+f"(c[2]), "+f"(c[3])
        : "r"(a[0]), "r"(a[1]), "r"(a[2]), "r"(a[3]), "r"(b[0]), "r"(b[1]));
}
__device__ __forceinline__ uint32_t pack_h2(float x, float y) {
    uint32_t r; asm("cvt.rn.f16x2.f32 %0, %1, %2;" : "=r"(r) : "f"(y), "f"(x));
    return r;
}
__device__ __forceinline__ uint32_t pack_b2(float x, float y) {
    uint32_t r; asm("cvt.rn.bf16x2.f32 %0, %1, %2;" : "=r"(r) : "f"(y), "f"(x));
    return r;
}

// ---------------------------------------------------------------------------
// Plain fp16 NT GEMM: C[i,j] = f( sum_k A[i,k]*B[j,k] ).
// 128x128x32 tile, 8 warps (32x64), 4-stage cp.async. Optional exp epilogue.
// Writes Ch (fp16) if non-null and Cf (f32) if non-null.
// REQUIRES: M,N mult 128; K mult 32; lda/ldb mult 8.
// ---------------------------------------------------------------------------
template <bool EXP>
__global__ __launch_bounds__(256, 2)
void gemm_h(const f16* __restrict__ A, const f16* __restrict__ B,
            f16* __restrict__ Ch, float* __restrict__ Cf,
            int K, int lda, int ldb, int ldc,
            size_t sA, size_t sB, size_t sC, float escale)
{
    extern __shared__ char dyn[];
    const uint32_t sm0 = smem_u32(dyn);
    const int tid  = threadIdx.x;
    const int lane = tid & 31;
    const int warp = tid >> 5;
    const int m0   = blockIdx.y * BM;
    const int n0   = blockIdx.x * BN;
    const int mb   = (warp & 3) * 32;
    const int nb   = (warp >> 2) * 64;

    A += (size_t)blockIdx.z * sA + (size_t)m0 * lda;
    B += (size_t)blockIdx.z * sB + (size_t)n0 * ldb;

    float acc[2][8][4];
#pragma unroll
    for (int mt = 0; mt < 2; mt++)
#pragma unroll
        for (int nt = 0; nt < 8; nt++)
#pragma unroll
            for (int r = 0; r < 4; r++) acc[mt][nt][r] = 0.f;

    auto load_stage = [&](int st, int ch) {
        const uint32_t sa = sm0 + st * STAGE_H;
        const uint32_t sb = sa + TILE_B;
        const f16* ga = A + ch * BK;
        const f16* gb = B + ch * BK;
#pragma unroll
        for (int t = 0; t < 2; t++) {
            int idx = t * 256 + tid;
            int r = idx >> 2, c = idx & 3;
            cp16(sa + r * 80 + c * 16, ga + (size_t)r * lda + c * 8);
            cp16(sb + r * 80 + c * 16, gb + (size_t)r * ldb + c * 8);
        }
        asm volatile("cp.async.commit_group;\n");
    };

    auto compute_stage = [&](int st) {
        const uint32_t sa = sm0 + st * STAGE_H;
        const uint32_t sb = sa + TILE_B;
#pragma unroll
        for (int ks = 0; ks < 2; ks++) {
            const int k0 = ks * 16;
            uint32_t a[2][4];
#pragma unroll
            for (int mt = 0; mt < 2; mt++) {
                int row = mb + mt * 16 + (lane & 7) + ((lane >> 3) & 1) * 8;
                int col = k0 + ((lane >> 4) & 1) * 8;
                ldsm4(a[mt][0], a[mt][1], a[mt][2], a[mt][3], sa + row * 80 + col * 2);
            }
            uint32_t b[8][2];
#pragma unroll
            for (int jp = 0; jp < 4; jp++) {
                int row = nb + jp * 16 + (lane & 7) + ((lane >> 4) & 1) * 8;
                int col = k0 + ((lane >> 3) & 1) * 8;
                ldsm4(b[2 * jp][0], b[2 * jp][1], b[2 * jp + 1][0], b[2 * jp + 1][1],
                      sb + row * 80 + col * 2);
            }
#pragma unroll
            for (int mt = 0; mt < 2; mt++)
#pragma unroll
                for (int nt = 0; nt < 8; nt++)
                    mma_f16m(acc[mt][nt], a[mt], b[nt]);
        }
    };

    const int nc = K / BK;
    load_stage(0, 0);
    load_stage(1, 1);
    load_stage(2, 2);
    for (int ch = 0; ch < nc; ch++) {
        if (ch < nc - 2)       asm volatile("cp.async.wait_group 2;\n");
        else if (ch == nc - 2) asm volatile("cp.async.wait_group 1;\n");
        else                   asm volatile("cp.async.wait_group 0;\n");
        __syncthreads();
        compute_stage(ch & 3);
        if (ch + 3 < nc) load_stage((ch + 3) & 3, ch + 3);
    }

    const int r0 = m0 + mb + (lane >> 2);
    const int c0 = n0 + nb + 2 * (lane & 3);
#pragma unroll
    for (int mt = 0; mt < 2; mt++) {
#pragma unroll
        for (int nt = 0; nt < 8; nt++) {
            const int row = r0 + mt * 16;
            const int col = c0 + nt * 8;
            float v0 = acc[mt][nt][0], v1 = acc[mt][nt][1];
            float v2 = acc[mt][nt][2], v3 = acc[mt][nt][3];
            if (EXP) {
                v0 = __expf(escale * v0); v1 = __expf(escale * v1);
                v2 = __expf(escale * v2); v3 = __expf(escale * v3);
            }
            if (Ch) {
                f16* p = Ch + (size_t)blockIdx.z * sC;
                *reinterpret_cast<uint32_t*>(p + (size_t)row * ldc + col)       = pack_h2(v0, v1);
                *reinterpret_cast<uint32_t*>(p + (size_t)(row + 8) * ldc + col) = pack_h2(v2, v3);
            }
            if (Cf) {
                float* p = Cf + (size_t)blockIdx.z * sC;
                *reinterpret_cast<float2*>(p + (size_t)row * ldc + col)       = make_float2(v0, v1);
                *reinterpret_cast<float2*>(p + (size_t)(row + 8) * ldc + col) = make_float2(v2, v3);
            }
        }
    }
}

// ---------------------------------------------------------------------------
// Split bf16 NT GEMM (hi/lo operands, 3 MMAs): near-fp32 operand precision.
// Writes Cf (f32, optional bias) and Ch (fp16) if non-null.
// ---------------------------------------------------------------------------
template <bool BIAS>
__global__ __launch_bounds__(256, 1)
void gemm_s(const bf16* __restrict__ Ah, const bf16* __restrict__ Al,
            const bf16* __restrict__ Bh, const bf16* __restrict__ Bl,
            float* __restrict__ Cf, f16* __restrict__ Ch,
            int K, int lda, int ldb, int ldc,
            size_t sA, size_t sB, size_t sC, const float* __restrict__ bias)
{
    extern __shared__ char dyn[];
    const uint32_t sm0 = smem_u32(dyn);
    const int tid  = threadIdx.x;
    const int lane = tid & 31;
    const int warp = tid >> 5;
    const int m0   = blockIdx.y * BM;
    const int n0   = blockIdx.x * BN;
    const int mb   = (warp & 3) * 32;
    const int nb   = (warp >> 2) * 64;

    const size_t aoff = (size_t)blockIdx.z * sA + (size_t)m0 * lda;
    const size_t boff = (size_t)blockIdx.z * sB + (size_t)n0 * ldb;
    Ah += aoff; Al += aoff; Bh += boff; Bl += boff;

    float acc[2][8][4];
#pragma unroll
    for (int mt = 0; mt < 2; mt++)
#pragma unroll
        for (int nt = 0; nt < 8; nt++)
#pragma unroll
            for (int r = 0; r < 4; r++) acc[mt][nt][r] = 0.f;

    auto load_stage = [&](int st, int ch) {
        const uint32_t s0 = sm0 + st * STAGE_S;
        const int kk = ch * BK;
#pragma unroll
        for (int t = 0; t < 2; t++) {
            int idx = t * 256 + tid;
            int r = idx >> 2, c = idx & 3;
            size_t go = (size_t)r * lda + kk + c * 8;
            cp16(s0 + 0 * TILE_B + r * 80 + c * 16, Ah + go);
            cp16(s0 + 1 * TILE_B + r * 80 + c * 16, Al + go);
            size_t gb = (size_t)r * ldb + kk + c * 8;
            cp16(s0 + 2 * TILE_B + r * 80 + c * 16, Bh + gb);
            cp16(s0 + 3 * TILE_B + r * 80 + c * 16, Bl + gb);
        }
        asm volatile("cp.async.commit_group;\n");
    };

    auto compute_stage = [&](int st) {
        const uint32_t s0 = sm0 + st * STAGE_S;
#pragma unroll
        for (int ks = 0; ks < 2; ks++) {
            const int k0 = ks * 16;
            uint32_t ah[2][4], al[2][4];
#pragma unroll
            for (int mt = 0; mt < 2; mt++) {
                int row = mb + mt * 16 + (lane & 7) + ((lane >> 3) & 1) * 8;
                int co  = (k0 + ((lane >> 4) & 1) * 8) * 2;
                ldsm4(ah[mt][0], ah[mt][1], ah[mt][2], ah[mt][3], s0 + row * 80 + co);
                ldsm4(al[mt][0], al[mt][1], al[mt][2], al[mt][3], s0 + TILE_B + row * 80 + co);
            }
            uint32_t bh[8][2], bl[8][2];
#pragma unroll
            for (int jp = 0; jp < 4; jp++) {
                int row = nb + jp * 16 + (lane & 7) + ((lane >> 4) & 1) * 8;
                int co  = (k0 + ((lane >> 3) & 1) * 8) * 2;
                ldsm4(bh[2 * jp][0], bh[2 * jp][1], bh[2 * jp + 1][0], bh[2 * jp + 1][1],
                      s0 + 2 * TILE_B + row * 80 + co);
                ldsm4(bl[2 * jp][0], bl[2 * jp][1], bl[2 * jp + 1][0], bl[2 * jp + 1][1],
                      s0 + 3 * TILE_B + row * 80 + co);
            }
#pragma unroll
            for (int mt = 0; mt < 2; mt++)
#pragma unroll
                for (int nt = 0; nt < 8; nt++) {
                    mma_bfm(acc[mt][nt], ah[mt], bh[nt]);
                    mma_bfm(acc[mt][nt], ah[mt], bl[nt]);
                    mma_bfm(acc[mt][nt], al[mt], bh[nt]);
                }
        }
    };

    const int nc = K / BK;
    load_stage(0, 0);
    load_stage(1, 1);
    for (int ch = 0; ch < nc; ch++) {
        if (ch == nc - 1) asm volatile("cp.async.wait_group 0;\n");
        else              asm volatile("cp.async.wait_group 1;\n");
        __syncthreads();
        compute_stage(ch % NST_S);
        if (ch + 2 < nc) load_stage((ch + 2) % NST_S, ch + 2);
    }

    const int r0 = m0 + mb + (lane >> 2);
    const int c0 = n0 + nb + 2 * (lane & 3);
#pragma unroll
    for (int mt = 0; mt < 2; mt++) {
#pragma unroll
        for (int nt = 0; nt < 8; nt++) {
            const int row = r0 + mt * 16;
            const int col = c0 + nt * 8;
            float v0 = acc[mt][nt][0], v1 = acc[mt][nt][1];
            float v2 = acc[mt][nt][2], v3 = acc[mt][nt][3];
            if (BIAS) {
                const float b0 = bias[col], b1 = bias[col + 1];
                v0 += b0; v1 += b1; v2 += b0; v3 += b1;
            }
            if (Cf) {
                float* p = Cf + (size_t)blockIdx.z * sC;
                *reinterpret_cast<float2*>(p + (size_t)row * ldc + col)       = make_float2(v0, v1);
                *reinterpret_cast<float2*>(p + (size_t)(row + 8) * ldc + col) = make_float2(v2, v3);
            }
            if (Ch) {
                f16* p = Ch + (size_t)blockIdx.z * sC;
                *reinterpret_cast<uint32_t*>(p + (size_t)row * ldc + col)       = pack_h2(v0, v1);
                *reinterpret_cast<uint32_t*>(p + (size_t)(row + 8) * ldc + col) = pack_h2(v2, v3);
            }
        }
    }
}

// ---------------------------------------------------------------------------
// Elementwise / utility kernels
// ---------------------------------------------------------------------------
__device__ __forceinline__ void split_bf(float v, bf16& h, bf16& l) {
    h = __float2bfloat16(v);
    l = __float2bfloat16(v - __bfloat162float(h));
}

__global__ void split_k(const float* __restrict__ in, bf16* __restrict__ oh,
                        bf16* __restrict__ ol, size_t n)
{
    for (size_t i = (size_t)blockIdx.x * blockDim.x + threadIdx.x; i < n;
         i += (size_t)gridDim.x * blockDim.x) {
        bf16 h, l; split_bf(in[i], h, l);
        oh[i] = h; ol[i] = l;
    }
}

// M1 = split(X .* YZt); dn[row] = rowsum (f32). One block per row (2048 elems).
__global__ void fuse_m1_k(const float* __restrict__ X, const float* __restrict__ YZt,
                          bf16* __restrict__ Mh, bf16* __restrict__ Ml,
                          float* __restrict__ dn)
{
    const size_t row = blockIdx.x;
    const float4* xr = reinterpret_cast<const float4*>(X  + row * CN);
    const float4* yr = reinterpret_cast<const float4*>(YZt + row * CN);
    const int i = threadIdx.x;      // 256 threads x 8
    float s = 0.f;
    uint4 hv, lv;
    uint32_t* hp = reinterpret_cast<uint32_t*>(&hv);
    uint32_t* lp = reinterpret_cast<uint32_t*>(&lv);
#pragma unroll
    for (int q = 0; q < 2; q++) {
        float4 a = xr[2 * i + q];
        float4 b = yr[2 * i + q];
        float m0 = a.x * b.x, m1 = a.y * b.y, m2 = a.z * b.z, m3 = a.w * b.w;
        s += (m0 + m1) + (m2 + m3);
        bf16 h0, l0, h1, l1, h2, l2, h3, l3;
        split_bf(m0, h0, l0); split_bf(m1, h1, l1);
        split_bf(m2, h2, l2); split_bf(m3, h3, l3);
        hp[2 * q]     = pack_b2(__bfloat162float(h0), __bfloat162float(h1));
        hp[2 * q + 1] = pack_b2(__bfloat162float(h2), __bfloat162float(h3));
        lp[2 * q]     = pack_b2(__bfloat162float(l0), __bfloat162float(l1));
        lp[2 * q + 1] = pack_b2(__bfloat162float(l2), __bfloat162float(l3));
    }
    reinterpret_cast<uint4*>(Mh + row * CN)[i] = hv;
    reinterpret_cast<uint4*>(Ml + row * CN)[i] = lv;
#pragma unroll
    for (int o = 16; o; o >>= 1) s += __shfl_down_sync(0xffffffffu, s, o);
    __shared__ float sm[8];
    if ((threadIdx.x & 31) == 0) sm[threadIdx.x >> 5] = s;
    __syncthreads();
    if (threadIdx.x < 8) {
        s = sm[threadIdx.x];
#pragma unroll
        for (int o = 4; o; o >>= 1) s += __shfl_down_sync(0xffu, s, o);
        if (threadIdx.x == 0) dn[row] = s;
    }
}

// M2 = split(XY .* Zt)
__global__ void fuse_m2_k(const float* __restrict__ XY, const float* __restrict__ Zt,
                          bf16* __restrict__ Mh, bf16* __restrict__ Ml)
{
    const size_t n4 = (size_t)CB * CN * CN / 4;
    const float4* a = reinterpret_cast<const float4*>(XY);
    const float4* b = reinterpret_cast<const float4*>(Zt);
    for (size_t i = (size_t)blockIdx.x * blockDim.x + threadIdx.x; i < n4;
         i += (size_t)gridDim.x * blockDim.x) {
        float4 x = a[i], z = b[i];
        float m0 = x.x * z.x, m1 = x.y * z.y, m2 = x.z * z.z, m3 = x.w * z.w;
        bf16 h0, l0, h1, l1, h2, l2, h3, l3;
        split_bf(m0, h0, l0); split_bf(m1, h1, l1);
        split_bf(m2, h2, l2); split_bf(m3, h3, l3);
        uint2 hv, lv;
        hv.x = pack_b2(__bfloat162float(h0), __bfloat162float(h1));
        hv.y = pack_b2(__bfloat162float(h2), __bfloat162float(h3));
        lv.x = pack_b2(__bfloat162float(l0), __bfloat162float(l1));
        lv.y = pack_b2(__bfloat162float(l2), __bfloat162float(l3));
        reinterpret_cast<uint2*>(Mh)[i] = hv;
        reinterpret_cast<uint2*>(Ml)[i] = lv;
    }
}

// vt[b][c][r] = P[b][r][col0+c], split to hi/lo
__global__ void tr_k(const float* __restrict__ P, bf16* __restrict__ vh,
                     bf16* __restrict__ vl, int col0)
{
    __shared__ float t[32][33];
    const int b  = blockIdx.z;
    const int c0 = blockIdx.x * 32;
    const int r0 = blockIdx.y * 32;
    const int tx = threadIdx.x, ty = threadIdx.y;
    const float* src = P + (size_t)b * CN * C5;
#pragma unroll
    for (int k = 0; k < 4; k++)
        t[ty + 8 * k][tx] = src[(size_t)(r0 + ty + 8 * k) * C5 + col0 + c0 + tx];
    __syncthreads();
#pragma unroll
    for (int k = 0; k < 4; k++) {
        float v = t[tx][ty + 8 * k];
        bf16 h, l; split_bf(v, h, l);
        size_t o = (size_t)b * CD * CN + (size_t)(c0 + ty + 8 * k) * CN + r0 + tx;
        vh[o] = h; vl[o] = l;
    }
}

__global__ void build_u_k(const float* __restrict__ n1, const float* __restrict__ n2,
                          const float* __restrict__ den, bf16* __restrict__ uh,
                          bf16* __restrict__ ul)
{
    const size_t total = (size_t)CB * CN * C2;
    for (size_t i = (size_t)blockIdx.x * blockDim.x + threadIdx.x; i < total;
         i += (size_t)gridDim.x * blockDim.x) {
        const size_t row = i >> 10;
        const int    c   = (int)(i & 1023);
        const float  d   = den[row];
        const float  v   = (c < CD) ? n1[row * CD + c] : n2[row * CD + (c - CD)];
        bf16 h, l; split_bf(v / d, h, l);
        uh[i] = h; ul[i] = l;
    }
}

// ---------------------------------------------------------------------------
extern "C" void kernel_launch(void* const* d_in, const int* in_sizes, int n_in,
                              void* d_out, int out_size)
{
    const float* x  = (const float*)d_in[0];
    const float* w  = (const float*)d_in[1];
    const float* ow = (const float*)d_in[2];
    const float* ob = (const float*)d_in[3];
    float* out = (float*)d_out;

    bf16 *xh, *xl, *wh, *wl, *owh, *owl, *M1h, *M1l, *M2h, *M2l;
    bf16 *v1th, *v1tl, *v2th, *v2tl, *uh, *ul;
    f16  *P16, *X16, *Y16, *Yt16, *Zt16;
    float *Pf, *Xf, *Ztf, *XYf, *YZtf, *n1, *n2, *dn;
    cudaGetSymbolAddress((void**)&xh,  g_xh);   cudaGetSymbolAddress((void**)&xl,  g_xl);
    cudaGetSymbolAddress((void**)&wh,  g_wh);   cudaGetSymbolAddress((void**)&wl,  g_wl);
    cudaGetSymbolAddress((void**)&owh, g_owh);  cudaGetSymbolAddress((void**)&owl, g_owl);
    cudaGetSymbolAddress((void**)&P16, g_P16);  cudaGetSymbolAddress((void**)&Pf,  g_Pf);
    cudaGetSymbolAddress((void**)&X16, g_X16);  cudaGetSymbolAddress((void**)&Xf,  g_Xf);
    cudaGetSymbolAddress((void**)&Y16, g_Y16);  cudaGetSymbolAddress((void**)&Yt16, g_Yt16);
    cudaGetSymbolAddress((void**)&Zt16, g_Zt16); cudaGetSymbolAddress((void**)&Ztf, g_Ztf);
    cudaGetSymbolAddress((void**)&XYf, g_XYf);  cudaGetSymbolAddress((void**)&YZtf, g_YZtf);
    cudaGetSymbolAddress((void**)&M1h, g_M1h);  cudaGetSymbolAddress((void**)&M1l, g_M1l);
    cudaGetSymbolAddress((void**)&M2h, g_M2h);  cudaGetSymbolAddress((void**)&M2l, g_M2l);
    cudaGetSymbolAddress((void**)&v1th, g_v1th); cudaGetSymbolAddress((void**)&v1tl, g_v1tl);
    cudaGetSymbolAddress((void**)&v2th, g_v2th); cudaGetSymbolAddress((void**)&v2tl, g_v2tl);
    cudaGetSymbolAddress((void**)&n1,  g_n1);   cudaGetSymbolAddress((void**)&n2,  g_n2);
    cudaGetSymbolAddress((void**)&dn,  g_dn);
    cudaGetSymbolAddress((void**)&uh,  g_uh);   cudaGetSymbolAddress((void**)&ul,  g_ul);

    cudaFuncSetAttribute(gemm_h<true>,  cudaFuncAttributeMaxDynamicSharedMemorySize, SMEM_H);
    cudaFuncSetAttribute(gemm_h<false>, cudaFuncAttributeMaxDynamicSharedMemorySize, SMEM_H);
    cudaFuncSetAttribute(gemm_s<true>,  cudaFuncAttributeMaxDynamicSharedMemorySize, SMEM_S);
    cudaFuncSetAttribute(gemm_s<false>, cudaFuncAttributeMaxDynamicSharedMemorySize, SMEM_S);

    const float scale = 1.0f / sqrtf((float)CD);
    const size_t sP  = (size_t)CN * C5;
    const size_t sNN = (size_t)CN * CN;
    const size_t sND = (size_t)CN * CD;
    const size_t sDN = (size_t)CD * CN;

    // 0. split inputs to bf16 hi/lo
    split_k<<<512, 256>>>(x,  xh,  xl,  (size_t)CB * CN * CD);
    split_k<<<512, 256>>>(w,  wh,  wl,  (size_t)C5 * CD);
    split_k<<<512, 256>>>(ow, owh, owl, (size_t)CD * C2);

    // 1. P = x @ w^T (split precision; dual write fp16 + f32)
    gemm_s<false><<<dim3(C5 / BN, (CB * CN) / BM, 1), 256, SMEM_S>>>(
        xh, xl, wh, wl, Pf, P16, CD, CD, CD, C5, 0, 0, 0, nullptr);

    // 2. Scores (fp16, exp): X=g(a,b)[+f32], Y=g(b,c), Yt=g(c,b), Zt=g(a,c)[+f32]
    dim3 gS(CN / BN, CN / BM, CB);
    gemm_h<true><<<gS, 256, SMEM_H>>>(P16 + 0 * CD, P16 + 1 * CD, X16, Xf,
        CD, C5, C5, CN, sP, sP, sNN, scale);
    gemm_h<true><<<gS, 256, SMEM_H>>>(P16 + 1 * CD, P16 + 2 * CD, Y16, nullptr,
        CD, C5, C5, CN, sP, sP, sNN, scale);
    gemm_h<true><<<gS, 256, SMEM_H>>>(P16 + 2 * CD, P16 + 1 * CD, Yt16, nullptr,
        CD, C5, C5, CN, sP, sP, sNN, scale);
    gemm_h<true><<<gS, 256, SMEM_H>>>(P16 + 0 * CD, P16 + 2 * CD, Zt16, Ztf,
        CD, C5, C5, CN, sP, sP, sNN, scale);

    // 3. YZt = NT(Zt, Y) (f32); XY = NT(X, Yt) (f32)  — positive sums, fp16 safe
    gemm_h<false><<<gS, 256, SMEM_H>>>(Zt16, Y16, nullptr, YZtf,
        CN, CN, CN, CN, sNN, sNN, sNN, 1.f);
    gemm_h<false><<<gS, 256, SMEM_H>>>(X16, Yt16, nullptr, XYf,
        CN, CN, CN, CN, sNN, sNN, sNN, 1.f);

    // 4. M1 = split(X .* YZt) + rowsum; M2 = split(XY .* Zt)
    fuse_m1_k<<<CB * CN, 256>>>(Xf, YZtf, M1h, M1l, dn);
    fuse_m2_k<<<4096, 256>>>(XYf, Ztf, M2h, M2l);

    // 5. v1t/v2t = split transposed P slices
    dim3 gT(CD / 32, CN / 32, CB), bT(32, 8);
    tr_k<<<gT, bT>>>(Pf, v1th, v1tl, 3 * CD);
    tr_k<<<gT, bT>>>(Pf, v2th, v2tl, 4 * CD);

    // 6. n1 = NT(M1, v1t); n2 = NT(M2, v2t)  (split precision, f32 out)
    dim3 gN(CD / BN, CN / BM, CB);
    gemm_s<false><<<gN, 256, SMEM_S>>>(M1h, M1l, v1th, v1tl, n1, nullptr,
        CN, CN, CN, CD, sNN, sDN, sND, nullptr);
    gemm_s<false><<<gN, 256, SMEM_S>>>(M2h, M2l, v2th, v2tl, n2, nullptr,
        CN, CN, CN, CD, sNN, sDN, sND, nullptr);

    // 7. u = split([n1/den, n2/den])
    build_u_k<<<2048, 256>>>(n1, n2, dn, uh, ul);

    // 8. out = NT(u, ow) + ob  (split precision, f32 out)
    gemm_s<true><<<dim3(CD / BN, (CB * CN) / BM, 1), 256, SMEM_S>>>(
        uh, ul, owh, owl, out, nullptr, C2, C2, C2, CD, 0, 0, 0, ob);
}

// round 6
// speedup vs baseline: 7.3084x; 1.5350x over previous
#include <cuda_runtime.h>
#include <cuda_fp16.h>
#include <math.h>
#include <stdint.h>

// Problem constants (fixed: B=4, N=2048, DIM=512, H=1)
#define CB 4
#define CN 2048
#define CD 512
#define C5 (5 * CD)   // 2560
#define C2 (2 * CD)   // 1024

#define BM 128
#define BN 128
#define BK 32
#define TILE_B (128 * 80)            // one operand tile: 128 rows x 80 B
#define STAGE_B (2 * TILE_B)         // A + B
#define NST 4
#define SMEM_G (NST * STAGE_B)       // 81920

typedef __half f16;

// ---------------------------------------------------------------------------
// Scratch (__device__ globals)
// ---------------------------------------------------------------------------
static __device__ f16   g_x16 [(size_t)CB * CN * CD];
static __device__ f16   g_w16 [(size_t)C5 * CD];
static __device__ f16   g_ow16[(size_t)CD * C2];
static __device__ f16   g_P16 [(size_t)CB * CN * C5];
static __device__ f16   g_X16 [(size_t)CB * CN * CN];
static __device__ f16   g_Y16 [(size_t)CB * CN * CN];
static __device__ f16   g_Yt16[(size_t)CB * CN * CN];
static __device__ f16   g_Zt16[(size_t)CB * CN * CN];
static __device__ f16   g_XY16[(size_t)CB * CN * CN];
static __device__ f16   g_YZt16[(size_t)CB * CN * CN];
static __device__ f16   g_M1  [(size_t)CB * CN * CN];
static __device__ f16   g_M2  [(size_t)CB * CN * CN];
static __device__ f16   g_v1t [(size_t)CB * CD * CN];
static __device__ f16   g_v2t [(size_t)CB * CD * CN];
static __device__ float g_n1  [(size_t)CB * CN * CD];
static __device__ float g_n2  [(size_t)CB * CN * CD];
static __device__ float g_dn  [(size_t)CB * CN];
static __device__ f16   g_u16 [(size_t)CB * CN * C2];

// ---------------------------------------------------------------------------
// PTX helpers
// ---------------------------------------------------------------------------
__device__ __forceinline__ uint32_t smem_u32(const void* p) {
    return (uint32_t)__cvta_generic_to_shared(p);
}
__device__ __forceinline__ void cp16(uint32_t s, const void* g) {
    asm volatile("cp.async.cg.shared.global [%0], [%1], 16;\n" :: "r"(s), "l"(g));
}
__device__ __forceinline__ void ldsm4(uint32_t& r0, uint32_t& r1, uint32_t& r2,
                                      uint32_t& r3, uint32_t a) {
    asm volatile("ldmatrix.sync.aligned.m8n8.x4.shared.b16 {%0,%1,%2,%3}, [%4];"
        : "=r"(r0), "=r"(r1), "=r"(r2), "=r"(r3) : "r"(a));
}
__device__ __forceinline__ void mma16(float* c, const uint32_t* a, const uint32_t* b) {
    asm volatile(
        "mma.sync.aligned.m16n8k16.row.col.f32.f16.f16.f32 "
        "{%0,%1,%2,%3}, {%4,%5,%6,%7}, {%8,%9}, {%0,%1,%2,%3};\n"
        : "+f"(c[0]), "+f"(c[1]), "+f"(c[2]), "+f"(c[3])
        : "r"(a[0]), "r"(a[1]), "r"(a[2]), "r"(a[3]), "r"(b[0]), "r"(b[1]));
}
__device__ __forceinline__ uint32_t pack_h2(float x, float y) {
    uint32_t r; asm("cvt.rn.f16x2.f32 %0, %1, %2;" : "=r"(r) : "f"(y), "f"(x));
    return r;
}

// ---------------------------------------------------------------------------
// fp16 tensor-core NT GEMM: C[i,j] = f( sum_k A[i,k]*B[j,k] ).
// 128x128x32 tile, 8 warps (32x64), 4-stage cp.async, fp32 accumulate.
// REQUIRES: M,N mult 128; K mult 32; lda/ldb mult 8.
// ---------------------------------------------------------------------------
template <bool EXP, bool BIAS, typename OutT>
__global__ __launch_bounds__(256, 2)
void gemm16(const f16* __restrict__ A, const f16* __restrict__ B,
            OutT* __restrict__ C, int K, int lda, int ldb, int ldc,
            size_t sA, size_t sB, size_t sC,
            float escale, const float* __restrict__ bias)
{
    extern __shared__ char dyn[];
    const uint32_t sm0 = smem_u32(dyn);
    const int tid  = threadIdx.x;
    const int lane = tid & 31;
    const int warp = tid >> 5;
    const int m0   = blockIdx.y * BM;
    const int n0   = blockIdx.x * BN;
    const int mb   = (warp & 3) * 32;
    const int nb   = (warp >> 2) * 64;

    A += (size_t)blockIdx.z * sA + (size_t)m0 * lda;
    B += (size_t)blockIdx.z * sB + (size_t)n0 * ldb;
    C += (size_t)blockIdx.z * sC;

    float acc[2][8][4];
#pragma unroll
    for (int mt = 0; mt < 2; mt++)
#pragma unroll
        for (int nt = 0; nt < 8; nt++)
#pragma unroll
            for (int r = 0; r < 4; r++) acc[mt][nt][r] = 0.f;

    auto load_stage = [&](int st, int ch) {
        const uint32_t sa = sm0 + st * STAGE_B;
        const uint32_t sb = sa + TILE_B;
        const f16* ga = A + ch * BK;
        const f16* gb = B + ch * BK;
#pragma unroll
        for (int t = 0; t < 2; t++) {
            int idx = t * 256 + tid;
            int r = idx >> 2, c = idx & 3;
            cp16(sa + r * 80 + c * 16, ga + (size_t)r * lda + c * 8);
            cp16(sb + r * 80 + c * 16, gb + (size_t)r * ldb + c * 8);
        }
        asm volatile("cp.async.commit_group;\n");
    };

    auto compute_stage = [&](int st) {
        const uint32_t sa = sm0 + st * STAGE_B;
        const uint32_t sb = sa + TILE_B;
#pragma unroll
        for (int ks = 0; ks < 2; ks++) {
            const int k0 = ks * 16;
            uint32_t a[2][4];
#pragma unroll
            for (int mt = 0; mt < 2; mt++) {
                int row = mb + mt * 16 + (lane & 7) + ((lane >> 3) & 1) * 8;
                int col = k0 + ((lane >> 4) & 1) * 8;
                ldsm4(a[mt][0], a[mt][1], a[mt][2], a[mt][3], sa + row * 80 + col * 2);
            }
            uint32_t b[8][2];
#pragma unroll
            for (int jp = 0; jp < 4; jp++) {
                int row = nb + jp * 16 + (lane & 7) + ((lane >> 4) & 1) * 8;
                int col = k0 + ((lane >> 3) & 1) * 8;
                ldsm4(b[2 * jp][0], b[2 * jp][1], b[2 * jp + 1][0], b[2 * jp + 1][1],
                      sb + row * 80 + col * 2);
            }
#pragma unroll
            for (int mt = 0; mt < 2; mt++)
#pragma unroll
                for (int nt = 0; nt < 8; nt++)
                    mma16(acc[mt][nt], a[mt], b[nt]);
        }
    };

    const int nc = K / BK;
    load_stage(0, 0);
    load_stage(1, 1);
    load_stage(2, 2);
    for (int ch = 0; ch < nc; ch++) {
        if (ch < nc - 2)       asm volatile("cp.async.wait_group 2;\n");
        else if (ch == nc - 2) asm volatile("cp.async.wait_group 1;\n");
        else                   asm volatile("cp.async.wait_group 0;\n");
        __syncthreads();
        compute_stage(ch & 3);
        if (ch + 3 < nc) load_stage((ch + 3) & 3, ch + 3);
    }

    const int r0 = m0 + mb + (lane >> 2);
    const int c0 = n0 + nb + 2 * (lane & 3);
#pragma unroll
    for (int mt = 0; mt < 2; mt++) {
#pragma unroll
        for (int nt = 0; nt < 8; nt++) {
            const int row = r0 + mt * 16;
            const int col = c0 + nt * 8;
            float v0 = acc[mt][nt][0], v1 = acc[mt][nt][1];
            float v2 = acc[mt][nt][2], v3 = acc[mt][nt][3];
            if (EXP) {
                v0 = __expf(escale * v0); v1 = __expf(escale * v1);
                v2 = __expf(escale * v2); v3 = __expf(escale * v3);
            }
            if (BIAS) {
                const float b0 = bias[col], b1 = bias[col + 1];
                v0 += b0; v1 += b1; v2 += b0; v3 += b1;
            }
            if (sizeof(OutT) == 2) {
                f16* p = (f16*)C;
                *reinterpret_cast<uint32_t*>(p + (size_t)row * ldc + col)       = pack_h2(v0, v1);
                *reinterpret_cast<uint32_t*>(p + (size_t)(row + 8) * ldc + col) = pack_h2(v2, v3);
            } else {
                float* p = (float*)C;
                *reinterpret_cast<float2*>(p + (size_t)row * ldc + col)       = make_float2(v0, v1);
                *reinterpret_cast<float2*>(p + (size_t)(row + 8) * ldc + col) = make_float2(v2, v3);
            }
        }
    }
}

// ---------------------------------------------------------------------------
// Elementwise / utility kernels
// ---------------------------------------------------------------------------
__global__ void round16_k(const float* __restrict__ in, f16* __restrict__ out, size_t n)
{
    for (size_t i = (size_t)blockIdx.x * blockDim.x + threadIdx.x; i < n;
         i += (size_t)gridDim.x * blockDim.x)
        out[i] = __float2half_rn(in[i]);
}

// dst[b][c][r] = src[b][r][off + c]   (fp16 transpose; grid: (C/32, R/32, B))
__global__ void trh_k(const f16* __restrict__ src, f16* __restrict__ dst,
                      int ld_s, int ld_d, size_t sbs, size_t sbd, int off)
{
    __shared__ f16 t[32][33];
    const int b  = blockIdx.z;
    const int c0 = blockIdx.x * 32;
    const int r0 = blockIdx.y * 32;
    const int tx = threadIdx.x, ty = threadIdx.y;
    src += (size_t)b * sbs;
    dst += (size_t)b * sbd;
#pragma unroll
    for (int k = 0; k < 4; k++)
        t[ty + 8 * k][tx] = src[(size_t)(r0 + ty + 8 * k) * ld_s + off + c0 + tx];
    __syncthreads();
#pragma unroll
    for (int k = 0; k < 4; k++)
        dst[(size_t)(c0 + ty + 8 * k) * ld_d + r0 + tx] = t[tx][ty + 8 * k];
}

// M1 = fp16(X .* YZt); dn[row] = f32 rowsum. One block per row, 256 threads x 8.
__global__ void fuse_m1_k(const f16* __restrict__ X, const f16* __restrict__ YZt,
                          f16* __restrict__ M1, float* __restrict__ dn)
{
    const size_t row = blockIdx.x;
    const uint4* xr = reinterpret_cast<const uint4*>(X   + row * CN);
    const uint4* yr = reinterpret_cast<const uint4*>(YZt + row * CN);
    const int i = threadIdx.x;
    uint4 xa = xr[i], ya = yr[i];
    uint32_t* xp = reinterpret_cast<uint32_t*>(&xa);
    const uint32_t* yp = reinterpret_cast<const uint32_t*>(&ya);
    float s = 0.f;
#pragma unroll
    for (int j = 0; j < 4; j++) {
        float2 xf = __half22float2(*reinterpret_cast<__half2*>(&xp[j]));
        float2 yf = __half22float2(*reinterpret_cast<const __half2*>(&yp[j]));
        float p0 = xf.x * yf.x, p1 = xf.y * yf.y;
        s += p0 + p1;
        xp[j] = pack_h2(p0, p1);
    }
    reinterpret_cast<uint4*>(M1 + row * CN)[i] = xa;
#pragma unroll
    for (int o = 16; o; o >>= 1) s += __shfl_down_sync(0xffffffffu, s, o);
    __shared__ float sm[8];
    if ((threadIdx.x & 31) == 0) sm[threadIdx.x >> 5] = s;
    __syncthreads();
    if (threadIdx.x < 8) {
        s = sm[threadIdx.x];
#pragma unroll
        for (int o = 4; o; o >>= 1) s += __shfl_down_sync(0xffu, s, o);
        if (threadIdx.x == 0) dn[row] = s;
    }
}

// M2 = fp16(XY .* Zt)
__global__ void fuse_m2_k(const f16* __restrict__ XY, const f16* __restrict__ Zt,
                          f16* __restrict__ M2)
{
    const size_t n8 = (size_t)CB * CN * CN / 8;
    const uint4* a = reinterpret_cast<const uint4*>(XY);
    const uint4* b = reinterpret_cast<const uint4*>(Zt);
    for (size_t i = (size_t)blockIdx.x * blockDim.x + threadIdx.x; i < n8;
         i += (size_t)gridDim.x * blockDim.x) {
        uint4 xa = a[i], za = b[i];
        uint32_t* xp = reinterpret_cast<uint32_t*>(&xa);
        const uint32_t* zp = reinterpret_cast<const uint32_t*>(&za);
#pragma unroll
        for (int j = 0; j < 4; j++) {
            float2 xf = __half22float2(*reinterpret_cast<__half2*>(&xp[j]));
            float2 zf = __half22float2(*reinterpret_cast<const __half2*>(&zp[j]));
            xp[j] = pack_h2(xf.x * zf.x, xf.y * zf.y);
        }
        reinterpret_cast<uint4*>(M2)[i] = xa;
    }
}

__global__ void build_u_k(const float* __restrict__ n1, const float* __restrict__ n2,
                          const float* __restrict__ den, f16* __restrict__ u)
{
    const size_t total = (size_t)CB * CN * C2;
    for (size_t i = (size_t)blockIdx.x * blockDim.x + threadIdx.x; i < total;
         i += (size_t)gridDim.x * blockDim.x) {
        const size_t row = i >> 10;
        const int    c   = (int)(i & 1023);
        const float  d   = den[row];
        const float  v   = (c < CD) ? n1[row * CD + c] : n2[row * CD + (c - CD)];
        u[i] = __float2half_rn(v / d);
    }
}

// ---------------------------------------------------------------------------
extern "C" void kernel_launch(void* const* d_in, const int* in_sizes, int n_in,
                              void* d_out, int out_size)
{
    const float* x  = (const float*)d_in[0];
    const float* w  = (const float*)d_in[1];
    const float* ow = (const float*)d_in[2];
    const float* ob = (const float*)d_in[3];
    float* out = (float*)d_out;

    f16 *x16, *w16, *ow16, *P16, *X16, *Y16, *Yt16, *Zt16, *XY16, *YZt16;
    f16 *M1, *M2, *v1t, *v2t, *u16;
    float *n1, *n2, *dn;
    cudaGetSymbolAddress((void**)&x16,  g_x16);
    cudaGetSymbolAddress((void**)&w16,  g_w16);
    cudaGetSymbolAddress((void**)&ow16, g_ow16);
    cudaGetSymbolAddress((void**)&P16,  g_P16);
    cudaGetSymbolAddress((void**)&X16,  g_X16);
    cudaGetSymbolAddress((void**)&Y16,  g_Y16);
    cudaGetSymbolAddress((void**)&Yt16, g_Yt16);
    cudaGetSymbolAddress((void**)&Zt16, g_Zt16);
    cudaGetSymbolAddress((void**)&XY16, g_XY16);
    cudaGetSymbolAddress((void**)&YZt16, g_YZt16);
    cudaGetSymbolAddress((void**)&M1,   g_M1);
    cudaGetSymbolAddress((void**)&M2,   g_M2);
    cudaGetSymbolAddress((void**)&v1t,  g_v1t);
    cudaGetSymbolAddress((void**)&v2t,  g_v2t);
    cudaGetSymbolAddress((void**)&n1,   g_n1);
    cudaGetSymbolAddress((void**)&n2,   g_n2);
    cudaGetSymbolAddress((void**)&dn,   g_dn);
    cudaGetSymbolAddress((void**)&u16,  g_u16);

    cudaFuncSetAttribute(gemm16<false, false, f16>,
                         cudaFuncAttributeMaxDynamicSharedMemorySize, SMEM_G);
    cudaFuncSetAttribute(gemm16<true, false, f16>,
                         cudaFuncAttributeMaxDynamicSharedMemorySize, SMEM_G);
    cudaFuncSetAttribute(gemm16<false, false, float>,
                         cudaFuncAttributeMaxDynamicSharedMemorySize, SMEM_G);
    cudaFuncSetAttribute(gemm16<false, true, float>,
                         cudaFuncAttributeMaxDynamicSharedMemorySize, SMEM_G);

    const float scale = 1.0f / sqrtf((float)CD);
    const size_t sP  = (size_t)CN * C5;
    const size_t sNN = (size_t)CN * CN;
    const size_t sND = (size_t)CN * CD;
    const size_t sDN = (size_t)CD * CN;

    // 0. RNE-round inputs to fp16
    round16_k<<<512, 256>>>(x,  x16,  (size_t)CB * CN * CD);
    round16_k<<<512, 256>>>(w,  w16,  (size_t)C5 * CD);
    round16_k<<<512, 256>>>(ow, ow16, (size_t)CD * C2);

    // 1. P = x @ w^T (fp16)
    gemm16<false, false, f16><<<dim3(C5 / BN, (CB * CN) / BM, 1), 256, SMEM_G>>>(
        x16, w16, P16, CD, CD, CD, C5, 0, 0, 0, 1.f, nullptr);

    // 2. Scores: X = exp(s a·b^T), Y = exp(s b·c^T), Zt = exp(s a·c^T)
    dim3 gS(CN / BN, CN / BM, CB);
    gemm16<true, false, f16><<<gS, 256, SMEM_G>>>(P16 + 0 * CD, P16 + 1 * CD, X16,
        CD, C5, C5, CN, sP, sP, sNN, scale, nullptr);
    gemm16<true, false, f16><<<gS, 256, SMEM_G>>>(P16 + 1 * CD, P16 + 2 * CD, Y16,
        CD, C5, C5, CN, sP, sP, sNN, scale, nullptr);
    gemm16<true, false, f16><<<gS, 256, SMEM_G>>>(P16 + 0 * CD, P16 + 2 * CD, Zt16,
        CD, C5, C5, CN, sP, sP, sNN, scale, nullptr);

    // 3. Yt = Y^T (exact transpose, cheaper than 4th score GEMM)
    trh_k<<<dim3(CN / 32, CN / 32, CB), dim3(32, 8)>>>(
        Y16, Yt16, CN, CN, sNN, sNN, 0);

    // 4. XY = NT(X, Yt) = X@Y ;  YZt = NT(Zt, Y) = (Y@Z)^T-rows
    gemm16<false, false, f16><<<gS, 256, SMEM_G>>>(X16, Yt16, XY16,
        CN, CN, CN, CN, sNN, sNN, sNN, 1.f, nullptr);
    gemm16<false, false, f16><<<gS, 256, SMEM_G>>>(Zt16, Y16, YZt16,
        CN, CN, CN, CN, sNN, sNN, sNN, 1.f, nullptr);

    // 5. M1 = fp16(X .* YZt) + f32 rowsum -> dn ;  M2 = fp16(XY .* Zt)
    fuse_m1_k<<<CB * CN, 256>>>(X16, YZt16, M1, dn);
    fuse_m2_k<<<4096, 256>>>(XY16, Zt16, M2);

    // 6. v1t/v2t = transposed P slices (fp16)
    dim3 gT(CD / 32, CN / 32, CB), bT(32, 8);
    trh_k<<<gT, bT>>>(P16, v1t, C5, CN, sP, sDN, 3 * CD);
    trh_k<<<gT, bT>>>(P16, v2t, C5, CN, sP, sDN, 4 * CD);

    // 7. n1 = NT(M1, v1t) ; n2 = NT(M2, v2t)   (f32 out)
    dim3 gN(CD / BN, CN / BM, CB);
    gemm16<false, false, float><<<gN, 256, SMEM_G>>>(M1, v1t, n1,
        CN, CN, CN, CD, sNN, sDN, sND, 1.f, nullptr);
    gemm16<false, false, float><<<gN, 256, SMEM_G>>>(M2, v2t, n2,
        CN, CN, CN, CD, sNN, sDN, sND, 1.f, nullptr);

    // 8. u = fp16([n1/den, n2/den])
    build_u_k<<<2048, 256>>>(n1, n2, dn, u16);

    // 9. out = NT(u, ow) + ob   (f32 out)
    gemm16<false, true, float><<<dim3(CD / BN, (CB * CN) / BM, 1), 256, SMEM_G>>>(
        u16, ow16, out, C2, C2, C2, CD, 0, 0, 0, 1.f, ob);
}